// round 5
// baseline (speedup 1.0000x reference)
#include <cuda_runtime.h>

#define Bn 256
#define EPS 1e-6f

typedef unsigned long long ull;

// ---- scratch (allocation-free rule: __device__ globals) ----
__device__ float g_metric[Bn * 256];       // symmetrized metric, (b,16,16)
__device__ float g_pa[Bn * 256];           // points@rW1[0:16] + rb1
__device__ float g_ar[Bn * 16 * 256];      // metric_row_i @ rW1[16:32]
__device__ float g_br[Bn * 16 * 256];      // metric_row_j @ rW1[32:48]
__device__ float g_spart[Bn * 16 * 256];   // partial relu-sums per (b,i)

__device__ __forceinline__ float tanh_fast(float x) {
    float y;
    asm("tanh.approx.f32 %0, %1;" : "=f"(y) : "f"(x));
    return y;
}
__device__ __forceinline__ ull pack2(float lo, float hi) {
    ull r;
    asm("mov.b64 %0, {%1, %2};" : "=l"(r) : "f"(lo), "f"(hi));
    return r;
}
__device__ __forceinline__ void unpack2(ull v, float& lo, float& hi) {
    asm("mov.b64 {%0, %1}, %2;" : "=f"(lo), "=f"(hi) : "l"(v));
}
__device__ __forceinline__ ull fma2(ull a, ull b, ull c) {
    ull d;
    asm("fma.rn.f32x2 %0, %1, %2, %3;" : "=l"(d) : "l"(a), "l"(b), "l"(c));
    return d;
}

// ---------------------------------------------------------------------------
// Kernel 1: per-batch metric MLP + linear precomputes for the ricci layer-1.
// grid = 256 (batch), block = 256. Weight loads hoisted to registers up front
// so their latency overlaps the serial metric MLP.
// ---------------------------------------------------------------------------
__global__ void __launch_bounds__(256) prep_kernel(
    const float* __restrict__ points,
    const float* __restrict__ mW1, const float* __restrict__ mb1,
    const float* __restrict__ mW2, const float* __restrict__ mb2,
    const float* __restrict__ rW1, const float* __restrict__ rb1)
{
    int b = blockIdx.x;
    int t = threadIdx.x;
    __shared__ float p_s[16];
    __shared__ float mh_s[128];
    __shared__ float raw_s[256];
    __shared__ float met_s[256];

    // hoisted loop-invariant weight loads (48 LDG in flight immediately)
    float wpr[16], w16r[16], w32r[16];
#pragma unroll
    for (int d = 0; d < 16; d++) {
        wpr[d]  = rW1[d * 256 + t];
        w16r[d] = rW1[(16 + d) * 256 + t];
        w32r[d] = rW1[(32 + d) * 256 + t];
    }
    float rb1t = rb1[t];

    if (t < 16) p_s[t] = points[b * 16 + t];
    __syncthreads();

    if (t < 128) {
        float a = mb1[t];
#pragma unroll
        for (int d = 0; d < 16; d++) a = fmaf(p_s[d], mW1[d * 128 + t], a);
        mh_s[t] = fmaxf(a, 0.f);
    }
    __syncthreads();

    {
        float a = mb2[t];
#pragma unroll 8
        for (int u = 0; u < 128; u++) a = fmaf(mh_s[u], mW2[u * 256 + t], a);
        raw_s[t] = a;
    }
    __syncthreads();

    {
        int i = t >> 4, j = t & 15;
        float m = 0.5f * (raw_s[i * 16 + j] + raw_s[j * 16 + i]);
        if (i == j) m += EPS;
        met_s[t] = m;
        g_metric[b * 256 + t] = m;
    }
    __syncthreads();

    // points @ rW1[0:16] + rb1
    {
        float a = rb1t;
#pragma unroll
        for (int d = 0; d < 16; d++) a = fmaf(p_s[d], wpr[d], a);
        g_pa[b * 256 + t] = a;
    }

    // Arow / Brow: metric row i through rW1 blocks [16:32] and [32:48]
#pragma unroll
    for (int i = 0; i < 16; i++) {
        float a = 0.f, c = 0.f;
#pragma unroll
        for (int d = 0; d < 16; d++) {
            float m = met_s[i * 16 + d];
            a = fmaf(m, w16r[d], a);
            c = fmaf(m, w32r[d], c);
        }
        g_ar[(b * 16 + i) * 256 + t] = a;
        g_br[(b * 16 + i) * 256 + t] = c;
    }
}

// ---------------------------------------------------------------------------
// Kernel 2: fused christoffel MLP + ricci layer-1 accumulate (f32x2 packed).
// grid = 4096 (b*16 + i), block = 256.
// ---------------------------------------------------------------------------
__global__ void __launch_bounds__(256) chris_ricci_kernel(
    const float* __restrict__ cW1, const float* __restrict__ cb1,
    const float* __restrict__ cW2, const float* __restrict__ cb2,
    const float* __restrict__ rW1)
{
    int bi = blockIdx.x;
    int b = bi >> 4, i = bi & 15;
    int t = threadIdx.x;

    __shared__ __align__(16) float met_s[256];
    __shared__ __align__(16) float ch_s[256];
    __shared__ __align__(16) float w1a_s[128];
    __shared__ __align__(16) float w1b_s[128];
    __shared__ __align__(16) float w1c_s[128];
    __shared__ __align__(16) float b1_s[128];
    __shared__ __align__(16) float w2_s[128];

    met_s[t] = g_metric[b * 256 + t];
    if (t < 128) { b1_s[t] = cb1[t]; w2_s[t] = cW2[t]; }
    else {
        int u = t - 128;
        w1a_s[u] = cW1[u];
        w1b_s[u] = cW1[128 + u];
        w1c_s[u] = cW1[256 + u];
    }
    __syncthreads();

    // ---- christoffel: input (m[i][j], m[j][k], m[i][k]) -> tanh(128) -> 1
    {
        int j = t >> 4, k = t & 15;
        ull X0 = pack2(met_s[i * 16 + j], met_s[i * 16 + j]);
        ull X1 = pack2(met_s[j * 16 + k], met_s[j * 16 + k]);
        ull X2 = pack2(met_s[i * 16 + k], met_s[i * 16 + k]);
        float a0 = 0.f, a1 = 0.f;
#pragma unroll 8
        for (int u = 0; u < 128; u += 2) {
            ull wa = *(const ull*)&w1a_s[u];
            ull wb = *(const ull*)&w1b_s[u];
            ull wc = *(const ull*)&w1c_s[u];
            ull bb = *(const ull*)&b1_s[u];
            ull v2 = fma2(wa, X0, fma2(wb, X1, fma2(wc, X2, bb)));
            float vlo, vhi; unpack2(v2, vlo, vhi);
            a0 = fmaf(tanh_fast(vlo), w2_s[u], a0);
            a1 = fmaf(tanh_fast(vhi), w2_s[u + 1], a1);
        }
        ch_s[t] = a0 + a1 + cb2[0];
    }
    __syncthreads();

    // ---- ricci layer-1: accumulate relu over j for hidden unit t (packed d)
    float pa = g_pa[b * 256 + t] + g_ar[bi * 256 + t];
    float brw[16];
    ull wp[8];
#pragma unroll
    for (int j = 0; j < 16; j++) brw[j] = g_br[(b * 16 + j) * 256 + t];
#pragma unroll
    for (int d2 = 0; d2 < 8; d2++)
        wp[d2] = pack2(rW1[(48 + 2 * d2) * 256 + t], rW1[(48 + 2 * d2 + 1) * 256 + t]);

    const ull* ch2 = (const ull*)ch_s;
    ull Z = pack2(0.f, 0.f);
    float sacc = 0.f;
#pragma unroll
    for (int j = 0; j < 16; j++) {
        ull acc2 = Z;
#pragma unroll
        for (int d2 = 0; d2 < 8; d2++) acc2 = fma2(ch2[j * 8 + d2], wp[d2], acc2);
        float alo, ahi; unpack2(acc2, alo, ahi);
        float v = (pa + brw[j]) + (alo + ahi);
        sacc += fmaxf(v, 0.f);
    }
    g_spart[bi * 256 + t] = sacc;
}

// ---------------------------------------------------------------------------
// Kernel 3: reduce partials, collapsed GEMM2, symmetrize.
// grid = 64, block = 256; each block handles 4 batches so rW2 is read
// 64x (16 MB L2 traffic) instead of 256x.
// ---------------------------------------------------------------------------
__global__ void __launch_bounds__(256) final_kernel(
    const float* __restrict__ rW2, const float* __restrict__ rb2,
    float* __restrict__ out)
{
    int b0 = blockIdx.x * 4;
    int t = threadIdx.x;
    __shared__ float s_s[4][256];
    __shared__ float S_s[4][256];

#pragma unroll
    for (int q = 0; q < 4; q++) {
        float s = 0.f;
#pragma unroll
        for (int i = 0; i < 16; i++) s += g_spart[((b0 + q) * 16 + i) * 256 + t];
        s_s[q][t] = s;
    }
    __syncthreads();

    float bias = 256.f * rb2[t];
    float a0 = bias, a1 = bias, a2 = bias, a3 = bias;
#pragma unroll 8
    for (int u = 0; u < 256; u++) {
        float w = rW2[u * 256 + t];
        a0 = fmaf(s_s[0][u], w, a0);
        a1 = fmaf(s_s[1][u], w, a1);
        a2 = fmaf(s_s[2][u], w, a2);
        a3 = fmaf(s_s[3][u], w, a3);
    }
    S_s[0][t] = a0; S_s[1][t] = a1; S_s[2][t] = a2; S_s[3][t] = a3;
    __syncthreads();

    int i = t >> 4, j = t & 15;
#pragma unroll
    for (int q = 0; q < 4; q++)
        out[(b0 + q) * 256 + t] = (S_s[q][t] + S_s[q][j * 16 + i]) * (0.5f / 256.f);
}

// ---------------------------------------------------------------------------
extern "C" void kernel_launch(void* const* d_in, const int* in_sizes, int n_in,
                              void* d_out, int out_size)
{
    const float* points = (const float*)d_in[0];
    const float* mW1 = (const float*)d_in[1];
    const float* mb1 = (const float*)d_in[2];
    const float* mW2 = (const float*)d_in[3];
    const float* mb2 = (const float*)d_in[4];
    const float* cW1 = (const float*)d_in[5];
    const float* cb1 = (const float*)d_in[6];
    const float* cW2 = (const float*)d_in[7];
    const float* cb2 = (const float*)d_in[8];
    const float* rW1 = (const float*)d_in[9];
    const float* rb1 = (const float*)d_in[10];
    const float* rW2 = (const float*)d_in[11];
    const float* rb2 = (const float*)d_in[12];
    float* out = (float*)d_out;

    prep_kernel<<<256, 256>>>(points, mW1, mb1, mW2, mb2, rW1, rb1);
    chris_ricci_kernel<<<4096, 256>>>(cW1, cb1, cW2, cb2, rW1);
    final_kernel<<<64, 256>>>(rW2, rb2, out);
}